// round 17
// baseline (speedup 1.0000x reference)
#include <cuda_runtime.h>
#include <cuda_fp16.h>
#include <math.h>
#include <stdint.h>

#define BSZ 4096
#define DIM 256
#define QSCALE 25.0f
#define QINV   0.04f

#define TILES_SELF 528
#define TILES_T1   1056
#define TILES_ALL  2080
#define TILE_ELEMS 16384
#define GRID_P     296                     // 2 CTAs/SM x 148 SMs (fully resident)
#define NTICK      (2 * TILES_ALL)

__device__ __align__(16) __half g_dist[(size_t)TILES_ALL * TILE_ELEMS];
__device__ __align__(16) char   g_q[2][BSZ * DIM];    // int8 quantized inputs
__device__ int    g_normi[2][BSZ];                    // |q|^2 (integer, exact)
__device__ double g_distsum[3];
__device__ double g_expsum[3];
__device__ unsigned int g_ticket;
__device__ unsigned int g_prep_done;
__device__ unsigned int g_zdone[3];
__device__ unsigned int g_done;

// ---------------------------------------------------------------------------
__global__ void zero_kernel() {
    int i = threadIdx.x;
    if (i < 3) { g_distsum[i] = 0.0; g_expsum[i] = 0.0; g_zdone[i] = 0u; }
    if (i == 3) { g_ticket = 0u; g_prep_done = 0u; g_done = 0u; }
}

// ---------------------------------------------------------------------------
__device__ __forceinline__ void tri_decode(int i, int& by, int& bx) {
    int b = 0;
    while (i >= 32 - b) { i -= 32 - b; b++; }
    by = b; bx = b + i;
}
// Ticket -> tile. Order: z=2 (1024), then z=0 (528 tri), then z=1 (528 tri).
// 'store' is the tile's slot in g_dist (matches historical layout).
__device__ __forceinline__ void map_ticket(int d, int& z, int& by, int& bx,
                                           float& w, int& store) {
    if (d < 1024)      { z = 2; by = d >> 5; bx = d & 31; store = TILES_T1 + d; w = 1.f; }
    else if (d < 1552) { z = 0; tri_decode(d - 1024, by, bx); store = d - 1024;
                         w = (by != bx) ? 2.f : 1.f; }
    else               { z = 1; tri_decode(d - 1552, by, bx); store = TILES_SELF + (d - 1552);
                         w = (by != bx) ? 2.f : 1.f; }
}

// ---------------------------------------------------------------------------
#define SMB_STRIDE 144
#define SMB_TILE   (128 * SMB_STRIDE)
#define SM_BYTES   (4 * SMB_TILE)          // 73728 bytes

__device__ __forceinline__ uint32_t smem_u32(const void* p) {
    uint32_t a;
    asm("{ .reg .u64 t; cvta.to.shared.u64 t, %1; cvt.u32.u64 %0, t; }" : "=r"(a) : "l"(p));
    return a;
}
__device__ __forceinline__ void mma_s8(int* c, const uint32_t* a, const uint32_t* b) {
    asm volatile(
        "mma.sync.aligned.m16n8k32.row.col.s32.s8.s8.s32 "
        "{%0,%1,%2,%3}, {%4,%5,%6,%7}, {%8,%9}, {%0,%1,%2,%3};"
        : "+r"(c[0]), "+r"(c[1]), "+r"(c[2]), "+r"(c[3])
        : "r"(a[0]), "r"(a[1]), "r"(a[2]), "r"(a[3]), "r"(b[0]), "r"(b[1]));
}

typedef unsigned long long ull_t;
__device__ __forceinline__ ull_t f2_pack(float lo, float hi) {
    ull_t r; asm("mov.b64 %0, {%1, %2};" : "=l"(r) : "f"(lo), "f"(hi)); return r;
}
__device__ __forceinline__ ull_t f2_mul(ull_t a, ull_t b) {
    ull_t r; asm("mul.rn.f32x2 %0, %1, %2;" : "=l"(r) : "l"(a), "l"(b)); return r;
}
__device__ __forceinline__ ull_t f2_add(ull_t a, ull_t b) {
    ull_t r; asm("add.rn.f32x2 %0, %1, %2;" : "=l"(r) : "l"(a), "l"(b)); return r;
}

// ---------------------------------------------------------------------------
// Persistent kernel: phase 0 = prep (quantize + norms) + resident-grid
// barrier; then ticket loop over 2080 dist tiles followed by 2080 exp tiles.
// dist = pure-IMMA 128x128 tile (proven R10 config). exp tiles gated on
// per-z dist completion counters; runs on MUFU/FMA while dist owns tensor.
__global__ void __launch_bounds__(256, 2)
mmd_kernel(const float* __restrict__ xs, const float* __restrict__ xt,
           float* __restrict__ out) {
    extern __shared__ char smc[];
    __shared__ double red[256];
    __shared__ unsigned s_ticket;

    const int tid = threadIdx.x;
    const int wid = tid >> 5;
    const int lid = tid & 31;

    // ---------------- Phase 0: prep (warp per row) ----------------
    for (int base = blockIdx.x * 8; base < 2 * BSZ; base += gridDim.x * 8) {
        int row = base + wid;
        int which = (row >= BSZ) ? 1 : 0;
        int r = row - which * BSZ;
        const float* src = (which ? xt : xs) + (size_t)r * DIM;
        float4 v0 = *(const float4*)(src + lid * 8);
        float4 v1 = *(const float4*)(src + lid * 8 + 4);
        float f[8] = {v0.x, v0.y, v0.z, v0.w, v1.x, v1.y, v1.z, v1.w};
        int q[8], nsum = 0;
        #pragma unroll
        for (int u = 0; u < 8; u++) {
            q[u] = __float2int_rn(fminf(fmaxf(f[u] * QSCALE, -127.f), 127.f));
            nsum += q[u] * q[u];
        }
        uint32_t lo = (q[0] & 255) | ((q[1] & 255) << 8) |
                      ((q[2] & 255) << 16) | ((uint32_t)(q[3] & 255) << 24);
        uint32_t hi = (q[4] & 255) | ((q[5] & 255) << 8) |
                      ((q[6] & 255) << 16) | ((uint32_t)(q[7] & 255) << 24);
        *(uint2*)(g_q[which] + (size_t)r * DIM + lid * 8) = make_uint2(lo, hi);
        #pragma unroll
        for (int o = 16; o > 0; o >>= 1)
            nsum += __shfl_xor_sync(0xffffffffu, nsum, o);
        if (lid == 0) g_normi[which][r] = nsum;
    }
    __threadfence();
    __syncthreads();
    if (tid == 0) {
        atomicAdd(&g_prep_done, 1u);
        while (*(volatile unsigned*)&g_prep_done < (unsigned)gridDim.x)
            __nanosleep(64);
    }
    __syncthreads();
    __threadfence();

    // ---------------- Ticket loop ----------------
    const uint32_t smb = smem_u32(smc);

    while (true) {
        if (tid == 0) s_ticket = atomicAdd(&g_ticket, 1u);
        __syncthreads();
        const int t = (int)s_ticket;
        if (t >= NTICK) break;

        if (t < TILES_ALL) {
            // ================= DIST tile (IMMA) =================
            int z, by, bx, store; float w;
            map_ticket(t, z, by, bx, w, store);
            const char* Am = g_q[(z == 1) ? 1 : 0];
            const char* Bm = g_q[(z == 0) ? 0 : 1];
            const int za = (z == 1) ? 1 : 0;
            const int zb = (z == 0) ? 0 : 1;
            const int rowBase = by * 128;
            const int colBase = bx * 128;

            const int wm = wid >> 2;
            const int wn = wid & 3;
            const int l4 = lid >> 2;
            const int lk = lid & 3;
            const int mrow0 = wm * 64;
            const int ncol0 = wn * 32;

            int acc[4][4][4];
            #pragma unroll
            for (int i = 0; i < 4; i++)
                #pragma unroll
                for (int j = 0; j < 4; j++)
                    #pragma unroll
                    for (int u = 0; u < 4; u++) acc[i][j][u] = 0;

            auto load_chunk = [&](int c, int buf) {
                const int k0 = c * 128;
                #pragma unroll
                for (int it = 0; it < 8; it++) {
                    int idx = it * 256 + tid;
                    int mat = idx >> 10;
                    int rem = idx & 1023;
                    int row = rem >> 3;
                    int g   = rem & 7;
                    const char* gp = (mat ? Bm : Am) +
                        (size_t)((mat ? colBase : rowBase) + row) * DIM + k0 + g * 16;
                    uint32_t sa = smb + (mat * 2 + buf) * SMB_TILE + row * SMB_STRIDE + g * 16;
                    asm volatile("cp.async.cg.shared.global [%0], [%1], 16;"
                                 :: "r"(sa), "l"(gp));
                }
                asm volatile("cp.async.commit_group;");
            };

            load_chunk(0, 0);
            #pragma unroll
            for (int c = 0; c < 2; c++) {
                if (c < 1) {
                    load_chunk(1, 1);
                    asm volatile("cp.async.wait_group 1;");
                } else {
                    asm volatile("cp.async.wait_group 0;");
                }
                __syncthreads();
                const char* A = smc + c * SMB_TILE;
                const char* B = smc + (2 + c) * SMB_TILE;
                #pragma unroll
                for (int ks = 0; ks < 4; ks++) {
                    const int kb = ks * 32;
                    uint32_t a[4][4], b[4][2];
                    #pragma unroll
                    for (int mt = 0; mt < 4; mt++) {
                        int r = mrow0 + mt * 16 + l4;
                        a[mt][0] = *(const uint32_t*)&A[r * SMB_STRIDE + kb + 4 * lk];
                        a[mt][1] = *(const uint32_t*)&A[(r + 8) * SMB_STRIDE + kb + 4 * lk];
                        a[mt][2] = *(const uint32_t*)&A[r * SMB_STRIDE + kb + 16 + 4 * lk];
                        a[mt][3] = *(const uint32_t*)&A[(r + 8) * SMB_STRIDE + kb + 16 + 4 * lk];
                    }
                    #pragma unroll
                    for (int nt = 0; nt < 4; nt++) {
                        int n = ncol0 + nt * 8 + l4;
                        b[nt][0] = *(const uint32_t*)&B[n * SMB_STRIDE + kb + 4 * lk];
                        b[nt][1] = *(const uint32_t*)&B[n * SMB_STRIDE + kb + 16 + 4 * lk];
                    }
                    #pragma unroll
                    for (int mt = 0; mt < 4; mt++)
                        #pragma unroll
                        for (int nt = 0; nt < 4; nt++)
                            mma_s8(acc[mt][nt], a[mt], b[nt]);
                }
                __syncthreads();
            }

            // Epilogue: 625*d^2 exact int; d = sqrt(.)/25; store fp16 + sum.
            int na0[4], na1[4], nb0[4], nb1[4];
            #pragma unroll
            for (int mt = 0; mt < 4; mt++) {
                int r = rowBase + mrow0 + mt * 16 + l4;
                na0[mt] = g_normi[za][r];
                na1[mt] = g_normi[za][r + 8];
            }
            #pragma unroll
            for (int nt = 0; nt < 4; nt++) {
                int cc = colBase + ncol0 + nt * 8 + 2 * lk;
                nb0[nt] = g_normi[zb][cc];
                nb1[nt] = g_normi[zb][cc + 1];
            }
            __half* gd = g_dist + (size_t)store * TILE_ELEMS;
            float lsum = 0.f;
            #pragma unroll
            for (int mt = 0; mt < 4; mt++) {
                int lr0 = mrow0 + mt * 16 + l4;
                #pragma unroll
                for (int nt = 0; nt < 4; nt++) {
                    int lc = ncol0 + nt * 8 + 2 * lk;
                    int* ac = acc[mt][nt];
                    float d00 = sqrtf((float)(na0[mt] + nb0[nt] - 2 * ac[0])) * QINV;
                    float d01 = sqrtf((float)(na0[mt] + nb1[nt] - 2 * ac[1])) * QINV;
                    float d10 = sqrtf((float)(na1[mt] + nb0[nt] - 2 * ac[2])) * QINV;
                    float d11 = sqrtf((float)(na1[mt] + nb1[nt] - 2 * ac[3])) * QINV;
                    lsum += (d00 + d01) + (d10 + d11);
                    *(__half2*)(gd + lr0 * 128 + lc)       = __floats2half2_rn(d00, d01);
                    *(__half2*)(gd + (lr0 + 8) * 128 + lc) = __floats2half2_rn(d10, d11);
                }
            }
            __threadfence();              // publish g_dist before zdone bump
            red[tid] = (double)lsum;
            __syncthreads();
            #pragma unroll
            for (int s = 128; s > 0; s >>= 1) {
                if (tid < s) red[tid] += red[tid + s];
                __syncthreads();
            }
            if (tid == 0) {
                atomicAdd(&g_distsum[z], red[0] * (double)w);
                __threadfence();
                atomicAdd(&g_zdone[z], 1u);
            }
        } else {
            // ================= EXP tile =================
            int z, by, bx, store; float w;
            map_ticket(t - TILES_ALL, z, by, bx, w, store);
            const unsigned nz = (z == 2) ? 1024u : 528u;
            if (tid == 0) {
                while (*(volatile unsigned*)&g_zdone[z] < nz) __nanosleep(128);
            }
            __syncthreads();
            __threadfence();

            double m = g_distsum[z] * (1.0 / ((double)BSZ * (double)BSZ));
            float c = (float)(-1.4426950408889634 / (4.0 * m));

            const uint4* src = (const uint4*)(g_dist + (size_t)store * TILE_ELEMS);
            uint4 v[8];
            #pragma unroll
            for (int it = 0; it < 8; it++) v[it] = src[it * 256 + tid];

            ull_t s2 = 0ull;
            #pragma unroll
            for (int it = 0; it < 8; it++) {
                uint32_t ww[4] = {v[it].x, v[it].y, v[it].z, v[it].w};
                #pragma unroll
                for (int u = 0; u < 4; u++) {
                    float2 f = __half22float2(*(__half2*)&ww[u]);
                    float e0, e1;
                    asm("ex2.approx.ftz.f32 %0, %1;" : "=f"(e0) : "f"(f.x * c));
                    asm("ex2.approx.ftz.f32 %0, %1;" : "=f"(e1) : "f"(f.y * c));
                    ull_t e  = f2_pack(e0, e1);
                    ull_t q2 = f2_mul(e, e);
                    ull_t q4 = f2_mul(q2, q2);
                    ull_t q8 = f2_mul(q4, q4);
                    ull_t q16 = f2_mul(q8, q8);
                    s2 = f2_add(s2, f2_add(f2_add(e, q2), f2_add(q4, q8)));
                    s2 = f2_add(s2, q16);
                }
            }
            float sl, sh;
            asm("mov.b64 {%0, %1}, %2;" : "=f"(sl), "=f"(sh) : "l"(s2));
            red[tid] = (double)(sl + sh);
            __syncthreads();
            #pragma unroll
            for (int s = 128; s > 0; s >>= 1) {
                if (tid < s) red[tid] += red[tid + s];
                __syncthreads();
            }
            if (tid == 0) {
                atomicAdd(&g_expsum[z], red[0] * (double)w);
                __threadfence();
                unsigned prev = atomicAdd(&g_done, 1u);
                if (prev == TILES_ALL - 1) {
                    double total = g_expsum[0] + g_expsum[1] - 2.0 * g_expsum[2];
                    double vv = total / ((double)BSZ * ((double)BSZ - 1.0));
                    float loss = sqrtf((float)vv);
                    out[0] = isnan(loss) ? 0.f : loss;
                }
            }
        }
    }
}

// ---------------------------------------------------------------------------
extern "C" void kernel_launch(void* const* d_in, const int* in_sizes, int n_in,
                              void* d_out, int out_size) {
    const float* xs = (const float*)d_in[0];
    const float* xt = (const float*)d_in[1];
    float* out = (float*)d_out;

    static int configured = 0;
    if (!configured) {
        cudaFuncSetAttribute(mmd_kernel,
                             cudaFuncAttributeMaxDynamicSharedMemorySize, SM_BYTES);
        configured = 1;
    }

    zero_kernel<<<1, 32>>>();
    mmd_kernel<<<GRID_P, 256, SM_BYTES>>>(xs, xt, out);
}